// round 2
// baseline (speedup 1.0000x reference)
#include <cuda_runtime.h>
#include <cuda_bf16.h>
#include <math.h>

#define LSEQ   65536
#define NS     100      // STATE
#define S2     200      // 2*STATE
#define XD     300      // 2*STATE + EMB
#define G4     400      // 4*STATE
#define NV     128      // VOCAB
#define LOG2E  1.4426950408889634f

// ---------------- device scratch (static globals: allocation-free) ----------------
__device__ __align__(128) float g_imT [LSEQ * S2];   // [l][j]   52.4 MB
__device__ __align__(128) float g_w1dt[LSEQ * NS];   // [l][a]   26.2 MB
__device__ float g_WihT[XD * G4];                    // [j][k]
__device__ float g_WhhT[NS * G4];                    // [j][k]
__device__ float g_bias[G4];                         // b_ih + b_hh
__device__ float g_linT[NS * NV];                    // [j][v]
__device__ float g_w1T [S2 * NS];                    // [j][a]
__device__ float g_w2T [S2 * NS];                    // [j][a]
__device__ float g_w2dt[NS];
__device__ float g_expC;                             // M = sum|v| + |v_b|
__device__ float g_partZ[256];
__device__ float g_partCtx[256 * S2];
__device__ unsigned g_barCnt;
__device__ unsigned g_barGen;

// ---------------- helpers ----------------
__device__ __forceinline__ float ex2fast(float x) {
    float y; asm("ex2.approx.f32 %0, %1;" : "=f"(y) : "f"(x)); return y;
}
// accurate tanh via ex2 + rcp (max err ~1e-7), FMA/MUFU balanced
__device__ __forceinline__ float tanh_acc(float x) {
    x = fminf(10.f, fmaxf(-10.f, x));
    float t;
    asm("ex2.approx.f32 %0, %1;" : "=f"(t) : "f"(x * 2.885390081777927f)); // e^{2x}
    float r;
    asm("rcp.approx.f32 %0, %1;" : "=f"(r) : "f"(t + 1.f));
    return (t - 1.f) * r;
}
__device__ __forceinline__ float sigf(float x) { return 1.f / (1.f + expf(-x)); }

// grid-wide sense barrier; all blocks resident (grid == #SMs, 1 block/SM)
__device__ __forceinline__ void gbar(int nb) {
    __threadfence();
    __syncthreads();
    if (threadIdx.x == 0) {
        unsigned gen = *((volatile unsigned*)&g_barGen);
        if (atomicAdd(&g_barCnt, 1u) == (unsigned)(nb - 1)) {
            g_barCnt = 0u;
            __threadfence();
            atomicAdd(&g_barGen, 1u);
        } else {
            while (*((volatile unsigned*)&g_barGen) == gen) { }
        }
    }
    __syncthreads();
}

// ---------------- precompute: weight transposes + bias fold + exp offset ----------------
__global__ void k_pre0(const float* __restrict__ Wih, const float* __restrict__ Whh,
                       const float* __restrict__ bih, const float* __restrict__ bhh,
                       const float* __restrict__ w1,  const float* __restrict__ w2,
                       const float* __restrict__ linw,
                       const float* __restrict__ vw,  const float* __restrict__ vb) {
    int tid = blockIdx.x * blockDim.x + threadIdx.x;
    int nt  = gridDim.x * blockDim.x;
    for (int i = tid; i < G4 * XD; i += nt) { int k = i / XD, j = i - k * XD; g_WihT[j * G4 + k] = Wih[i]; }
    for (int i = tid; i < G4 * NS; i += nt) { int k = i / NS, j = i - k * NS; g_WhhT[j * G4 + k] = Whh[i]; }
    for (int i = tid; i < G4;       i += nt) g_bias[i] = bih[i] + bhh[i];
    for (int i = tid; i < NV * NS;  i += nt) { int v = i / NS, j = i - v * NS; g_linT[j * NV + v] = linw[i]; }
    for (int i = tid; i < NS * S2;  i += nt) {
        int a = i / S2, j = i - a * S2;
        g_w1T[j * NS + a] = w1[i];
        g_w2T[j * NS + a] = w2[i];
    }
    if (tid == 0) {
        float s = fabsf(vb[0]);
        for (int a = 0; a < NS; a++) s += fabsf(vw[a]);
        g_expC = s;
    }
}

// ---------------- precompute: transpose input_mat [200][L] -> imT [L][200] ----------------
__global__ void k_pre1(const float* __restrict__ im) {
    __shared__ float tile[32][33];
    int tx = threadIdx.x, ty = threadIdx.y;
    int l0 = blockIdx.x * 32, j0 = blockIdx.y * 32;
    int j = j0 + ty;
    if (j < S2) tile[ty][tx] = im[(size_t)j * LSEQ + l0 + tx];
    __syncthreads();
    int jw = j0 + tx;
    if (jw < S2) g_imT[(size_t)(l0 + ty) * S2 + jw] = tile[tx][ty];
}

// ---------------- precompute: w1dt[l][a] = sum_j imT[l][j] * w1T[j][a] ----------------
__global__ void k_pre2() {
    __shared__ __align__(16) float rows[8][200];
    int tid = threadIdx.x;
    for (int l0 = blockIdx.x * 8; l0 < LSEQ; l0 += gridDim.x * 8) {
        for (int idx = tid; idx < 8 * 200; idx += 128)
            rows[idx / 200][idx % 200] = g_imT[(size_t)l0 * S2 + idx];
        __syncthreads();
        if (tid < NS) {
            float acc[8];
            #pragma unroll
            for (int li = 0; li < 8; li++) acc[li] = 0.f;
            for (int j = 0; j < 200; j += 4) {
                float w0v = g_w1T[(j + 0) * NS + tid];
                float w1v = g_w1T[(j + 1) * NS + tid];
                float w2v = g_w1T[(j + 2) * NS + tid];
                float w3v = g_w1T[(j + 3) * NS + tid];
                #pragma unroll
                for (int li = 0; li < 8; li++) {
                    float4 r = *(const float4*)&rows[li][j];
                    acc[li] += r.x * w0v + r.y * w1v + r.z * w2v + r.w * w3v;
                }
            }
            #pragma unroll
            for (int li = 0; li < 8; li++)
                g_w1dt[(size_t)(l0 + li) * NS + tid] = acc[li];
        }
        __syncthreads();
    }
}

// ---------------- persistent main kernel ----------------
__global__ void __launch_bounds__(512, 1) k_main(
    const int*   __restrict__ ids,
    const float* __restrict__ vw,   const float* __restrict__ vb,
    const float* __restrict__ linb, const float* __restrict__ emb,
    const int*   __restrict__ eosp, float* __restrict__ out, int T)
{
    const int tid  = threadIdx.x, lane = tid & 31, wid = tid >> 5;
    const int bid  = blockIdx.x,  nb   = gridDim.x;
    const int nwarp = nb * 16;
    const int gw    = bid * 16 + wid;

    __shared__ __align__(16) float s_wctx[16 * 200];
    __shared__ float s_wz[16];
    __shared__ float s_x[XD + 4];
    __shared__ float s_g[G4];
    __shared__ float s_h[NS];
    __shared__ float s_c[NS];
    __shared__ float s_lg[NV];
    __shared__ float s_Z;
    __shared__ float s_loss;

    const float vv0 = vw[lane], vv1 = vw[lane + 32], vv2 = vw[lane + 64];
    const float vv3 = (lane < 4) ? vw[96 + lane] : 0.f;
    const float vb0 = vb[0];
    const float Moff = g_expC;
    const int   eos = eosp ? *eosp : 0;

    // ---- priming step (block 0): x0 = [zeros(200), emb[eos]], h=c=0 ----
    if (bid == 0) {
        for (int j = tid; j < S2; j += 512) s_x[j] = 0.f;
        for (int j = tid; j < NS; j += 512) { s_x[S2 + j] = emb[eos * NS + j]; s_h[j] = 0.f; s_c[j] = 0.f; }
        if (tid == 0) s_loss = 0.f;
        __syncthreads();
        if (tid < G4) {
            float acc = g_bias[tid];
            for (int j = 0; j < XD; j++) acc += g_WihT[j * G4 + tid] * s_x[j];
            for (int j = 0; j < NS; j++) acc += g_WhhT[j * G4 + tid] * s_h[j];
            s_g[tid] = acc;
        }
        __syncthreads();
        if (tid < NS) {
            float gi = s_g[tid], gf = s_g[NS + tid], gg = s_g[2 * NS + tid], go = s_g[3 * NS + tid];
            float cn = sigf(gf) * s_c[tid] + sigf(gi) * tanhf(gg);
            s_c[tid] = cn;
            s_h[tid] = sigf(go) * tanhf(cn);
        }
        __syncthreads();
        if (tid < NS) {
            float acc = 0.f;
            for (int j = 0; j < NS; j++) acc += g_w2T[j * NS + tid] * s_h[j];
            for (int j = 0; j < NS; j++) acc += g_w2T[(NS + j) * NS + tid] * s_c[j];
            g_w2dt[tid] = acc;
        }
    }

    // ---- decoder steps ----
    for (int t = 0; t < T; t++) {
        gbar(nb);   // w2dt for step t is published

        // attention over this warp's share of L
        float w0  = __ldcg(&g_w2dt[lane]);
        float w1s = __ldcg(&g_w2dt[lane + 32]);
        float w2s = __ldcg(&g_w2dt[lane + 64]);
        float w3s = (lane < 4) ? __ldcg(&g_w2dt[96 + lane]) : 0.f;
        float cx0 = 0, cx1 = 0, cx2 = 0, cx3 = 0, cx4 = 0, cx5 = 0, cx6 = 0, z = 0;
        for (int l = gw; l < LSEQ; l += nwarp) {
            const float* wr = g_w1dt + (size_t)l * NS;
            float a0 = __ldg(wr + lane), a1 = __ldg(wr + lane + 32), a2 = __ldg(wr + lane + 64);
            float p = vv0 * tanh_acc(a0 + w0) + vv1 * tanh_acc(a1 + w1s) + vv2 * tanh_acc(a2 + w2s);
            if (lane < 4) p += vv3 * tanh_acc(__ldg(wr + 96 + lane) + w3s);
            p += __shfl_xor_sync(0xffffffffu, p, 16);
            p += __shfl_xor_sync(0xffffffffu, p, 8);
            p += __shfl_xor_sync(0xffffffffu, p, 4);
            p += __shfl_xor_sync(0xffffffffu, p, 2);
            p += __shfl_xor_sync(0xffffffffu, p, 1);
            float e = ex2fast((p + vb0 - Moff) * LOG2E);   // exponent <= 0, no max-scan needed
            const float* ir = g_imT + (size_t)l * S2;
            cx0 += e * __ldg(ir + lane);
            cx1 += e * __ldg(ir + lane + 32);
            cx2 += e * __ldg(ir + lane + 64);
            cx3 += e * __ldg(ir + lane + 96);
            cx4 += e * __ldg(ir + lane + 128);
            cx5 += e * __ldg(ir + lane + 160);
            if (lane < 8) cx6 += e * __ldg(ir + 192 + lane);
            z += e;
        }
        // block reduce -> per-block partials
        {
            float* wc = s_wctx + wid * 200;
            wc[lane] = cx0; wc[lane + 32] = cx1; wc[lane + 64] = cx2;
            wc[lane + 96] = cx3; wc[lane + 128] = cx4; wc[lane + 160] = cx5;
            if (lane < 8) wc[192 + lane] = cx6;
            if (lane == 0) s_wz[wid] = z;
        }
        __syncthreads();
        if (tid < S2) {
            float acc = 0.f;
            #pragma unroll
            for (int w = 0; w < 16; w++) acc += s_wctx[w * 200 + tid];
            g_partCtx[bid * S2 + tid] = acc;
        }
        if (tid == 0) {
            float az = 0.f;
            #pragma unroll
            for (int w = 0; w < 16; w++) az += s_wz[w];
            g_partZ[bid] = az;
        }
        gbar(nb);   // all partials visible

        // serial phase: block 0 only
        if (bid == 0) {
            if (tid < S2) {
                float acc = 0.f;
                for (int b = 0; b < nb; b++) acc += __ldcg(&g_partCtx[b * S2 + tid]);
                s_x[tid] = acc;
            }
            if (tid == 0) {
                float az = 0.f;
                for (int b = 0; b < nb; b++) az += __ldcg(&g_partZ[b]);
                s_Z = az;
            }
            int ch   = ids[t];
            int prev = (t == 0) ? eos : ids[t - 1];
            __syncthreads();
            float rz = 1.f / s_Z;
            if (tid < S2) s_x[tid] *= rz;                       // context
            if (tid < NS) s_x[S2 + tid] = emb[prev * NS + tid]; // last char embedding
            __syncthreads();
            if (tid < G4) {
                float acc = g_bias[tid];
                #pragma unroll 4
                for (int j = 0; j < XD; j++) acc += g_WihT[j * G4 + tid] * s_x[j];
                #pragma unroll 4
                for (int j = 0; j < NS; j++) acc += g_WhhT[j * G4 + tid] * s_h[j];
                s_g[tid] = acc;
            }
            __syncthreads();
            if (tid < NS) {
                float gi = s_g[tid], gf = s_g[NS + tid], gg = s_g[2 * NS + tid], go = s_g[3 * NS + tid];
                float cn = sigf(gf) * s_c[tid] + sigf(gi) * tanhf(gg);
                s_c[tid] = cn;
                s_h[tid] = sigf(go) * tanhf(cn);
            }
            __syncthreads();
            if (tid < NV) {
                float acc = linb[tid];
                for (int j = 0; j < NS; j++) acc += g_linT[j * NV + tid] * s_h[j];
                s_lg[tid] = acc;
            }
            if (tid < NS) {                                     // publish w2dt for step t+1
                float acc = 0.f;
                for (int j = 0; j < NS; j++) acc += g_w2T[j * NS + tid] * s_h[j];
                for (int j = 0; j < NS; j++) acc += g_w2T[(NS + j) * NS + tid] * s_c[j];
                g_w2dt[tid] = acc;
            }
            __syncthreads();
            if (wid == 0) {
                float m = fmaxf(fmaxf(s_lg[lane], s_lg[lane + 32]),
                                fmaxf(s_lg[lane + 64], s_lg[lane + 96]));
                m = fmaxf(m, __shfl_xor_sync(0xffffffffu, m, 16));
                m = fmaxf(m, __shfl_xor_sync(0xffffffffu, m, 8));
                m = fmaxf(m, __shfl_xor_sync(0xffffffffu, m, 4));
                m = fmaxf(m, __shfl_xor_sync(0xffffffffu, m, 2));
                m = fmaxf(m, __shfl_xor_sync(0xffffffffu, m, 1));
                float se = expf(s_lg[lane] - m) + expf(s_lg[lane + 32] - m)
                         + expf(s_lg[lane + 64] - m) + expf(s_lg[lane + 96] - m);
                se += __shfl_xor_sync(0xffffffffu, se, 16);
                se += __shfl_xor_sync(0xffffffffu, se, 8);
                se += __shfl_xor_sync(0xffffffffu, se, 4);
                se += __shfl_xor_sync(0xffffffffu, se, 2);
                se += __shfl_xor_sync(0xffffffffu, se, 1);
                if (lane == 0) s_loss += logf(se) + m - s_lg[ch];
            }
        }
    }
    if (bid == 0 && tid == 0) out[0] = s_loss;
}

// ---------------- launch ----------------
extern "C" void kernel_launch(void* const* d_in, const int* in_sizes, int n_in,
                              void* d_out, int out_size) {
    const float* im   = (const float*)d_in[0];
    const int*   ids  = (const int*)  d_in[1];
    const float* Wih  = (const float*)d_in[2];
    const float* Whh  = (const float*)d_in[3];
    const float* bih  = (const float*)d_in[4];
    const float* bhh  = (const float*)d_in[5];
    const float* w1   = (const float*)d_in[6];
    const float* w2   = (const float*)d_in[7];
    const float* vw   = (const float*)d_in[8];
    const float* vb   = (const float*)d_in[9];
    const float* linw = (const float*)d_in[10];
    const float* linb = (const float*)d_in[11];
    const float* emb  = (const float*)d_in[12];
    const int*   eosp = (n_in > 13) ? (const int*)d_in[13] : nullptr;
    const int T = in_sizes[1];

    int dev = 0, sm = 148;
    cudaGetDevice(&dev);
    cudaDeviceGetAttribute(&sm, cudaDevAttrMultiProcessorCount, dev);
    int nb = sm < 1 ? 1 : (sm > 256 ? 256 : sm);

    k_pre0<<<64, 256>>>(Wih, Whh, bih, bhh, w1, w2, linw, vw, vb);
    k_pre1<<<dim3(LSEQ / 32, 7), dim3(32, 32)>>>(im);
    k_pre2<<<2048, 128>>>();
    k_main<<<nb, 512>>>(ids, vw, vb, linb, emb, eosp, (float*)d_out, T);
}

// round 3
// speedup vs baseline: 1.8824x; 1.8824x over previous
#include <cuda_runtime.h>
#include <math.h>

#define LSEQ 65536
#define NS   100
#define S2   200
#define XD   300
#define G4   400
#define NV   128
#define PADB 152
#define LOG2E 1.4426950408889634f

// ---------------- device scratch ----------------
__device__ __align__(128) float g_imT [LSEQ * S2];   // [l][j]
__device__ __align__(128) float g_w1dt[LSEQ * NS];   // [l][a]
__device__ float g_w1T[S2 * NS];
__device__ float g_expC;
__device__ float g_partCtxT[S2 * PADB];              // [j][b]
__device__ __align__(16) float g_partZ[PADB];
__device__ float g_ctx[S2];
__device__ float g_Z;
__device__ float g_gates[G4];
__device__ __align__(16) float g_w2dt[NS];
__device__ float g_h[NS];
__device__ unsigned g_barCnt, g_barGen, g_ctxCnt, g_gateCnt;

// ---------------- helpers ----------------
__device__ __forceinline__ float ex2fast(float x) {
    float y; asm("ex2.approx.f32 %0, %1;" : "=f"(y) : "f"(x)); return y;
}
__device__ __forceinline__ float tanh_acc(float x) {
    x = fminf(10.f, fmaxf(-10.f, x));
    float t; asm("ex2.approx.f32 %0, %1;" : "=f"(t) : "f"(x * 2.885390081777927f));
    float r; asm("rcp.approx.f32 %0, %1;" : "=f"(r) : "f"(t + 1.f));
    return (t - 1.f) * r;
}
__device__ __forceinline__ float sigf(float x) { return 1.f / (1.f + expf(-x)); }
__device__ __forceinline__ float warp_bfly(float v) {
    v += __shfl_xor_sync(0xffffffffu, v, 16);
    v += __shfl_xor_sync(0xffffffffu, v, 8);
    v += __shfl_xor_sync(0xffffffffu, v, 4);
    v += __shfl_xor_sync(0xffffffffu, v, 2);
    v += __shfl_xor_sync(0xffffffffu, v, 1);
    return v;
}
__device__ __forceinline__ void gbar(int nb) {
    __threadfence();
    __syncthreads();
    if (threadIdx.x == 0) {
        unsigned gen = *((volatile unsigned*)&g_barGen);
        if (atomicAdd(&g_barCnt, 1u) == (unsigned)(nb - 1)) {
            g_barCnt = 0u;
            __threadfence();
            atomicAdd(&g_barGen, 1u);
        } else {
            while (*((volatile unsigned*)&g_barGen) == gen) { }
        }
    }
    __syncthreads();
}
__device__ __forceinline__ void cspin(unsigned* p, unsigned target) {
    if (threadIdx.x == 0) {
        while ((int)(*((volatile unsigned*)p) - target) < 0) { }
    }
    __syncthreads();
}

// ---------------- precompute ----------------
__global__ void k_pre0(const float* __restrict__ w1, const float* __restrict__ vw,
                       const float* __restrict__ vb) {
    int tid = blockIdx.x * blockDim.x + threadIdx.x;
    int nt  = gridDim.x * blockDim.x;
    for (int i = tid; i < NS * S2; i += nt) {
        int a = i / S2, j = i - a * S2;
        g_w1T[j * NS + a] = w1[i];
    }
    if (tid == 0) {
        float s = fabsf(vb[0]);
        for (int a = 0; a < NS; a++) s += fabsf(vw[a]);
        g_expC = s;
    }
}

__global__ void k_pre1(const float* __restrict__ im) {
    __shared__ float tile[32][33];
    int tx = threadIdx.x, ty = threadIdx.y;
    int l0 = blockIdx.x * 32, j0 = blockIdx.y * 32;
    int j = j0 + ty;
    if (j < S2) tile[ty][tx] = im[(size_t)j * LSEQ + l0 + tx];
    __syncthreads();
    int jw = j0 + tx;
    if (jw < S2) g_imT[(size_t)(l0 + ty) * S2 + jw] = tile[tx][ty];
}

__global__ void k_pre2() {
    __shared__ __align__(16) float rows[8][200];
    int tid = threadIdx.x;
    for (int l0 = blockIdx.x * 8; l0 < LSEQ; l0 += gridDim.x * 8) {
        for (int idx = tid; idx < 8 * 200; idx += 128)
            rows[idx / 200][idx % 200] = g_imT[(size_t)l0 * S2 + idx];
        __syncthreads();
        if (tid < NS) {
            float acc[8];
            #pragma unroll
            for (int li = 0; li < 8; li++) acc[li] = 0.f;
            for (int j = 0; j < 200; j += 4) {
                float w0v = g_w1T[(j + 0) * NS + tid];
                float w1v = g_w1T[(j + 1) * NS + tid];
                float w2v = g_w1T[(j + 2) * NS + tid];
                float w3v = g_w1T[(j + 3) * NS + tid];
                #pragma unroll
                for (int li = 0; li < 8; li++) {
                    float4 r = *(const float4*)&rows[li][j];
                    acc[li] += r.x * w0v + r.y * w1v + r.z * w2v + r.w * w3v;
                }
            }
            #pragma unroll
            for (int li = 0; li < 8; li++)
                g_w1dt[(size_t)(l0 + li) * NS + tid] = acc[li];
        }
        __syncthreads();
    }
}

// ---------------- persistent main kernel ----------------
__global__ void __launch_bounds__(512, 1) k_main(
    const int*   __restrict__ ids,
    const float* __restrict__ Wih,  const float* __restrict__ Whh,
    const float* __restrict__ bih,  const float* __restrict__ bhh,
    const float* __restrict__ w2,
    const float* __restrict__ vw,   const float* __restrict__ vb,
    const float* __restrict__ linw, const float* __restrict__ linb,
    const float* __restrict__ emb,  const int* __restrict__ eosp,
    float* __restrict__ out, int T)
{
    const int tid  = threadIdx.x, lane = tid & 31, wid = tid >> 5;
    const int bid  = blockIdx.x,  nb   = gridDim.x;
    const int nwarp = nb * 16;
    const int gw    = bid * 16 + wid;

    __shared__ __align__(16) float s_w[16 * 208];
    __shared__ float s_wz[16];
    __shared__ __align__(16) float s_h[NS];
    __shared__ __align__(16) float s_c[NS];
    __shared__ float s_lg[NV];
    __shared__ float s_g[G4];
    __shared__ float s_loss;

    const float vb0  = vb[0];
    const float Moff = g_expC;
    const int   eos  = eosp ? *eosp : 0;

    const unsigned ctxBase  = *((volatile unsigned*)&g_ctxCnt);
    const unsigned gateBase = *((volatile unsigned*)&g_gateCnt);

    const float4 zero4 = make_float4(0.f, 0.f, 0.f, 0.f);
    float4 vv4 = zero4;
    if (lane < 25) vv4 = __ldg((const float4*)vw + lane);

    // ---- priming step (block 0): x0 = [zeros(200), emb[eos]], h=c=0 ----
    if (bid == 0) {
        if (tid == 0) s_loss = 0.f;
        if (tid < G4) {
            const float4* wr = (const float4*)(Wih + tid * XD + S2);
            const float4* ev = (const float4*)(emb + eos * NS);
            float acc = __ldg(&bih[tid]) + __ldg(&bhh[tid]);
            #pragma unroll
            for (int i = 0; i < 25; i++) {
                float4 wv = __ldg(wr + i), xv = __ldg(ev + i);
                acc += wv.x * xv.x + wv.y * xv.y + wv.z * xv.z + wv.w * xv.w;
            }
            s_g[tid] = acc;
        }
        __syncthreads();
        if (tid < NS) {
            float gi = s_g[tid], gg = s_g[2 * NS + tid], go = s_g[3 * NS + tid];
            float cn = sigf(gi) * tanhf(gg);               // c was 0
            s_c[tid] = cn;
            float hh = sigf(go) * tanhf(cn);
            s_h[tid] = hh;
            g_h[tid] = hh;
        }
        __syncthreads();
        if (tid >= 128 && tid < 228) {
            int a = tid - 128;
            const float4* wrow = (const float4*)(w2 + a * S2);
            const float4* hv = (const float4*)s_h;
            const float4* cv = (const float4*)s_c;
            float acc = 0.f;
            #pragma unroll
            for (int i = 0; i < 25; i++) {
                float4 wv = __ldg(wrow + i), xv = hv[i];
                acc += wv.x * xv.x + wv.y * xv.y + wv.z * xv.z + wv.w * xv.w;
            }
            #pragma unroll
            for (int i = 0; i < 25; i++) {
                float4 wv = __ldg(wrow + 25 + i), xv = cv[i];
                acc += wv.x * xv.x + wv.y * xv.y + wv.z * xv.z + wv.w * xv.w;
            }
            g_w2dt[a] = acc;
        }
    }

    // ---- decoder steps ----
    for (int t = 0; t < T; t++) {
        gbar(nb);   // w2dt + h for step t published

        // ======= attention (all blocks, ILP2 + float4) =======
        float4 w2d4 = zero4;
        if (lane < 25) w2d4 = __ldcg((const float4*)g_w2dt + lane);
        float4 accA = zero4, accB = zero4;
        float zacc = 0.f;
        for (int l = gw; l < LSEQ; l += 2 * nwarp) {
            int l1 = l + nwarp;
            bool v1 = (l1 < LSEQ);
            float4 a0 = zero4, a1 = zero4;
            if (lane < 25) {
                a0 = __ldg((const float4*)(g_w1dt + (size_t)l * NS) + lane);
                if (v1) a1 = __ldg((const float4*)(g_w1dt + (size_t)l1 * NS) + lane);
            }
            const float4* ir0 = (const float4*)(g_imT + (size_t)l * S2);
            const float4* ir1 = (const float4*)(g_imT + (size_t)l1 * S2);
            float4 f0 = __ldg(ir0 + lane);
            float4 f1 = v1 ? __ldg(ir1 + lane) : zero4;
            float4 h0 = zero4, h1 = zero4;
            if (lane < 18) {
                h0 = __ldg(ir0 + 32 + lane);
                if (v1) h1 = __ldg(ir1 + 32 + lane);
            }
            float p0 = vv4.x * tanh_acc(a0.x + w2d4.x) + vv4.y * tanh_acc(a0.y + w2d4.y)
                     + vv4.z * tanh_acc(a0.z + w2d4.z) + vv4.w * tanh_acc(a0.w + w2d4.w);
            float p1 = vv4.x * tanh_acc(a1.x + w2d4.x) + vv4.y * tanh_acc(a1.y + w2d4.y)
                     + vv4.z * tanh_acc(a1.z + w2d4.z) + vv4.w * tanh_acc(a1.w + w2d4.w);
            p0 = warp_bfly(p0);
            p1 = warp_bfly(p1);
            float e0 = ex2fast((p0 + vb0 - Moff) * LOG2E);
            float e1 = v1 ? ex2fast((p1 + vb0 - Moff) * LOG2E) : 0.f;
            accA.x += e0 * f0.x + e1 * f1.x;
            accA.y += e0 * f0.y + e1 * f1.y;
            accA.z += e0 * f0.z + e1 * f1.z;
            accA.w += e0 * f0.w + e1 * f1.w;
            accB.x += e0 * h0.x + e1 * h1.x;
            accB.y += e0 * h0.y + e1 * h1.y;
            accB.z += e0 * h0.z + e1 * h1.z;
            accB.w += e0 * h0.w + e1 * h1.w;
            zacc += e0 + e1;
        }
        {
            float* wr = s_w + wid * 208;
            ((float4*)wr)[lane] = accA;
            if (lane < 18) ((float4*)wr)[32 + lane] = accB;
            if (lane == 0) s_wz[wid] = zacc;
        }
        __syncthreads();
        if (tid < S2) {
            float s = 0.f;
            #pragma unroll
            for (int w = 0; w < 16; w++) s += s_w[w * 208 + tid];
            g_partCtxT[tid * PADB + bid] = s;
        }
        if (tid == 0) {
            float s = 0.f;
            #pragma unroll
            for (int w = 0; w < 16; w++) s += s_wz[w];
            g_partZ[bid] = s;
        }

        gbar(nb);   // all partials visible

        // ======= context reduce (distributed, warp-per-j) =======
        if (wid == 0) {
            int j = bid;
            if (j < S2) {
                float s = 0.f;
                #pragma unroll
                for (int i = 0; i < 5; i++) {
                    int b = lane + 32 * i;
                    if (b < nb) s += __ldcg(&g_partCtxT[j * PADB + b]);
                }
                s = warp_bfly(s);
                if (lane == 0) g_ctx[j] = s;
            }
        } else if (wid == 1) {
            int j = bid + nb;
            if (j < S2) {
                float s = 0.f;
                #pragma unroll
                for (int i = 0; i < 5; i++) {
                    int b = lane + 32 * i;
                    if (b < nb) s += __ldcg(&g_partCtxT[j * PADB + b]);
                }
                s = warp_bfly(s);
                if (lane == 0) g_ctx[j] = s;
            }
        } else if (wid == 3 && bid == 0) {
            float s = 0.f;
            #pragma unroll
            for (int i = 0; i < 5; i++) {
                int b = lane + 32 * i;
                if (b < nb) s += __ldcg(&g_partZ[b]);
            }
            s = warp_bfly(s);
            if (lane == 0) g_Z = s;
        }
        __syncthreads();
        if (tid == 0) { __threadfence(); atomicAdd(&g_ctxCnt, 1u); }
        cspin(&g_ctxCnt, ctxBase + (unsigned)((t + 1) * nb));

        // ======= gates (distributed, warp-per-output, L1-resident rows) =======
        int prev = (t == 0) ? eos : __ldg(&ids[t - 1]);
        if (wid < 4) {
            int k = bid + wid * nb;
            if (k < G4) {
                float rz = 1.f / __ldcg(&g_Z);
                const float* wr = Wih + k * XD;
                float dc = 0.f, d0 = 0.f;
                #pragma unroll
                for (int i = 0; i < 7; i++) {
                    int j = lane + 32 * i;
                    if (j < S2) dc += __ldg(wr + j) * __ldcg(&g_ctx[j]);
                }
                const float* ep = emb + prev * NS;
                #pragma unroll
                for (int i = 0; i < 4; i++) {
                    int j = lane + 32 * i;
                    if (j < NS) d0 += __ldg(wr + S2 + j) * __ldg(ep + j);
                }
                const float* hr = Whh + k * NS;
                #pragma unroll
                for (int i = 0; i < 4; i++) {
                    int j = lane + 32 * i;
                    if (j < NS) d0 += __ldg(hr + j) * __ldcg(&g_h[j]);
                }
                dc = warp_bfly(dc);
                d0 = warp_bfly(d0);
                if (lane == 0)
                    g_gates[k] = fmaf(dc, rz, d0) + __ldg(&bih[k]) + __ldg(&bhh[k]);
            }
        }
        __syncthreads();
        if (tid == 0) { __threadfence(); atomicAdd(&g_gateCnt, 1u); }

        // ======= block-0 epilogue =======
        if (bid == 0) {
            cspin(&g_gateCnt, gateBase + (unsigned)((t + 1) * nb));
            if (tid < NS) {
                float gi = __ldcg(&g_gates[tid]);
                float gf = __ldcg(&g_gates[NS + tid]);
                float gg = __ldcg(&g_gates[2 * NS + tid]);
                float go = __ldcg(&g_gates[3 * NS + tid]);
                float cn = sigf(gf) * s_c[tid] + sigf(gi) * tanhf(gg);
                s_c[tid] = cn;
                float hh = sigf(go) * tanhf(cn);
                s_h[tid] = hh;
                g_h[tid] = hh;
            }
            __syncthreads();
            if (tid < NV) {
                const float4* lr = (const float4*)(linw + tid * NS);
                const float4* hv = (const float4*)s_h;
                float acc = __ldg(&linb[tid]);
                #pragma unroll
                for (int i = 0; i < 25; i++) {
                    float4 wv = __ldg(lr + i), xv = hv[i];
                    acc += wv.x * xv.x + wv.y * xv.y + wv.z * xv.z + wv.w * xv.w;
                }
                s_lg[tid] = acc;
            }
            if (tid >= 128 && tid < 228) {
                int a = tid - 128;
                const float4* wrow = (const float4*)(w2 + a * S2);
                const float4* hv = (const float4*)s_h;
                const float4* cv = (const float4*)s_c;
                float acc = 0.f;
                #pragma unroll
                for (int i = 0; i < 25; i++) {
                    float4 wv = __ldg(wrow + i), xv = hv[i];
                    acc += wv.x * xv.x + wv.y * xv.y + wv.z * xv.z + wv.w * xv.w;
                }
                #pragma unroll
                for (int i = 0; i < 25; i++) {
                    float4 wv = __ldg(wrow + 25 + i), xv = cv[i];
                    acc += wv.x * xv.x + wv.y * xv.y + wv.z * xv.z + wv.w * xv.w;
                }
                g_w2dt[a] = acc;
            }
            __syncthreads();
            if (wid == 0) {
                int ch = __ldg(&ids[t]);
                float m = fmaxf(fmaxf(s_lg[lane], s_lg[lane + 32]),
                                fmaxf(s_lg[lane + 64], s_lg[lane + 96]));
                m = fmaxf(m, __shfl_xor_sync(0xffffffffu, m, 16));
                m = fmaxf(m, __shfl_xor_sync(0xffffffffu, m, 8));
                m = fmaxf(m, __shfl_xor_sync(0xffffffffu, m, 4));
                m = fmaxf(m, __shfl_xor_sync(0xffffffffu, m, 2));
                m = fmaxf(m, __shfl_xor_sync(0xffffffffu, m, 1));
                float se = expf(s_lg[lane] - m) + expf(s_lg[lane + 32] - m)
                         + expf(s_lg[lane + 64] - m) + expf(s_lg[lane + 96] - m);
                se = warp_bfly(se);
                if (lane == 0) s_loss += logf(se) + m - s_lg[ch];
            }
        }
    }
    if (bid == 0 && tid == 0) out[0] = s_loss;
}

// ---------------- launch ----------------
extern "C" void kernel_launch(void* const* d_in, const int* in_sizes, int n_in,
                              void* d_out, int out_size) {
    const float* im   = (const float*)d_in[0];
    const int*   ids  = (const int*)  d_in[1];
    const float* Wih  = (const float*)d_in[2];
    const float* Whh  = (const float*)d_in[3];
    const float* bih  = (const float*)d_in[4];
    const float* bhh  = (const float*)d_in[5];
    const float* w1   = (const float*)d_in[6];
    const float* w2   = (const float*)d_in[7];
    const float* vw   = (const float*)d_in[8];
    const float* vb   = (const float*)d_in[9];
    const float* linw = (const float*)d_in[10];
    const float* linb = (const float*)d_in[11];
    const float* emb  = (const float*)d_in[12];
    const int*   eosp = (n_in > 13) ? (const int*)d_in[13] : nullptr;
    const int T = in_sizes[1];

    int dev = 0, sm = 148;
    cudaGetDevice(&dev);
    cudaDeviceGetAttribute(&sm, cudaDevAttrMultiProcessorCount, dev);
    int nb = sm < 1 ? 1 : (sm > 148 ? 148 : sm);

    k_pre0<<<64, 256>>>(w1, vw, vb);
    k_pre1<<<dim3(LSEQ / 32, 7), dim3(32, 32)>>>(im);
    k_pre2<<<2048, 128>>>();
    k_main<<<nb, 512>>>(ids, Wih, Whh, bih, bhh, w2, vw, vb, linw, linb, emb,
                        eosp, (float*)d_out, T);
}

// round 4
// speedup vs baseline: 2.1009x; 1.1161x over previous
#include <cuda_runtime.h>
#include <cuda_fp16.h>
#include <math.h>

#define LSEQ 65536
#define NS   100
#define S2   200
#define XD   300
#define G4   400
#define NV   128
#define NB   128          // main-kernel blocks (must all be co-resident; 148 SMs)
#define NT   2048         // LSEQ/32 tiles
#define NGRP 8
#define GS   16
#define LOG2E 1.4426950408889634f

// ---------------- device scratch ----------------
__device__ __align__(128) float   g_imT [LSEQ * S2];     // fp32 [l][j] (precompute intermediate)
__device__ __align__(128) float   g_w1dt[LSEQ * NS];     // fp32 [l][a] (precompute intermediate)
__device__ __align__(128) __half2 g_w1t [NT * 50 * 32];  // fp16 [tile][a2][lane]
__device__ __align__(128) __half2 g_imc [LSEQ * 100];    // fp16 [l][j2]
__device__ float g_w1T[S2 * NS];
__device__ float g_expC;
__device__ float g_partCtxT[S2 * NB];                    // [j][b]
__device__ __align__(16) float g_partZ[NB];
__device__ float g_ctx[S2];
__device__ float g_Z;
__device__ float g_gateA[G4];
__device__ float g_gateB[G4];
__device__ __align__(16) float g_w2dt[NS];
__device__ float g_h[NS];
__device__ unsigned g_grpCnt[NGRP * 32];                 // 128B-strided counters
__device__ unsigned g_rootCnt;
__device__ unsigned g_rootGen;

// ---------------- helpers ----------------
__device__ __forceinline__ float ex2fast(float x) {
    float y; asm("ex2.approx.f32 %0, %1;" : "=f"(y) : "f"(x)); return y;
}
__device__ __forceinline__ float tanhapx(float x) {
    float y; asm("tanh.approx.f32 %0, %1;" : "=f"(y) : "f"(x)); return y;
}
__device__ __forceinline__ float sigf(float x) { return 1.f / (1.f + expf(-x)); }
__device__ __forceinline__ float warp_bfly(float v) {
    v += __shfl_xor_sync(0xffffffffu, v, 16);
    v += __shfl_xor_sync(0xffffffffu, v, 8);
    v += __shfl_xor_sync(0xffffffffu, v, 4);
    v += __shfl_xor_sync(0xffffffffu, v, 2);
    v += __shfl_xor_sync(0xffffffffu, v, 1);
    return v;
}
__device__ __forceinline__ unsigned ldv(unsigned* p) { return *((volatile unsigned*)p); }

// tree barrier: 8 groups of 16, then root. ~1.3K cycles.
__device__ __forceinline__ void tbar(int bid) {
    __threadfence();
    __syncthreads();
    if (threadIdx.x == 0) {
        int g = bid >> 4;
        unsigned gen = ldv(&g_rootGen);
        if (atomicAdd(&g_grpCnt[g * 32], 1u) == GS - 1) {
            atomicExch(&g_grpCnt[g * 32], 0u);
            __threadfence();
            if (atomicAdd(&g_rootCnt, 1u) == NGRP - 1) {
                atomicExch(&g_rootCnt, 0u);
                __threadfence();
                atomicAdd(&g_rootGen, 1u);   // release
            } else {
                while (ldv(&g_rootGen) == gen) { }
            }
        } else {
            while (ldv(&g_rootGen) == gen) { }
        }
    }
    __syncthreads();
}

// ---------------- precompute ----------------
__global__ void k_pre0(const float* __restrict__ w1, const float* __restrict__ vw,
                       const float* __restrict__ vb) {
    int tid = blockIdx.x * blockDim.x + threadIdx.x;
    int nt  = gridDim.x * blockDim.x;
    for (int i = tid; i < NS * S2; i += nt) {
        int a = i / S2, j = i - a * S2;
        g_w1T[j * NS + a] = w1[i];
    }
    if (tid == 0) {
        float s = fabsf(vb[0]);
        for (int a = 0; a < NS; a++) s += fabsf(vw[a]);
        g_expC = s;
    }
}

__global__ void k_pre1(const float* __restrict__ im) {
    __shared__ float tile[32][33];
    int tx = threadIdx.x, ty = threadIdx.y;
    int l0 = blockIdx.x * 32, j0 = blockIdx.y * 32;
    int j = j0 + ty;
    if (j < S2) tile[ty][tx] = im[(size_t)j * LSEQ + l0 + tx];
    __syncthreads();
    int jw = j0 + tx;
    if (jw < S2) g_imT[(size_t)(l0 + ty) * S2 + jw] = tile[tx][ty];
}

__global__ void k_pre2() {
    __shared__ __align__(16) float rows[8][200];
    int tid = threadIdx.x;
    for (int l0 = blockIdx.x * 8; l0 < LSEQ; l0 += gridDim.x * 8) {
        for (int idx = tid; idx < 8 * 200; idx += 128)
            rows[idx / 200][idx % 200] = g_imT[(size_t)l0 * S2 + idx];
        __syncthreads();
        if (tid < NS) {
            float acc[8];
            #pragma unroll
            for (int li = 0; li < 8; li++) acc[li] = 0.f;
            for (int j = 0; j < 200; j += 4) {
                float w0v = g_w1T[(j + 0) * NS + tid];
                float w1v = g_w1T[(j + 1) * NS + tid];
                float w2v = g_w1T[(j + 2) * NS + tid];
                float w3v = g_w1T[(j + 3) * NS + tid];
                #pragma unroll
                for (int li = 0; li < 8; li++) {
                    float4 r = *(const float4*)&rows[li][j];
                    acc[li] += r.x * w0v + r.y * w1v + r.z * w2v + r.w * w3v;
                }
            }
            #pragma unroll
            for (int li = 0; li < 8; li++)
                g_w1dt[(size_t)(l0 + li) * NS + tid] = acc[li];
        }
        __syncthreads();
    }
}

// fp16 conversions: w1t tiled [tile][a2][lane]; imc row-major [l][j2]
__global__ void k_pre3() {
    int gid = blockIdx.x * blockDim.x + threadIdx.x;
    int nt  = gridDim.x * blockDim.x;
    for (int i = gid; i < NT * 1600; i += nt) {
        int tile = i / 1600, r = i - tile * 1600;
        int a2 = r >> 5, lane = r & 31;
        int l = tile * 32 + lane;
        g_w1t[i] = __floats2half2_rn(g_w1dt[(size_t)l * NS + 2 * a2],
                                     g_w1dt[(size_t)l * NS + 2 * a2 + 1]);
    }
    for (int i = gid; i < LSEQ * 100; i += nt) {
        g_imc[i] = __floats2half2_rn(g_imT[(size_t)2 * i], g_imT[(size_t)2 * i + 1]);
    }
}

// ---------------- persistent main kernel ----------------
__global__ void __launch_bounds__(512, 1) k_main(
    const int*   __restrict__ ids,
    const float* __restrict__ Wih,  const float* __restrict__ Whh,
    const float* __restrict__ bih,  const float* __restrict__ bhh,
    const float* __restrict__ w2,
    const float* __restrict__ vw,   const float* __restrict__ vb,
    const float* __restrict__ linw, const float* __restrict__ linb,
    const float* __restrict__ emb,  const int* __restrict__ eosp,
    float* __restrict__ out, int T)
{
    const int tid  = threadIdx.x, lane = tid & 31, wid = tid >> 5;
    const int bid  = blockIdx.x;
    const int tile = bid * 16 + wid;      // exactly one tile per warp

    __shared__ __align__(16) float s_w[16 * 208];
    __shared__ float s_e[16 * 33];
    __shared__ float s_wz[16];
    __shared__ __align__(16) float s_v[NS];
    __shared__ __align__(16) float s_w2dt[NS];
    __shared__ __align__(16) float s_h[NS];
    __shared__ __align__(16) float s_c[NS];
    __shared__ float s_lg[NV];
    __shared__ float s_g[G4];
    __shared__ float s_loss;

    const float vb0  = vb[0];
    const float Moff = g_expC;
    const int   eos  = eosp ? *eosp : 0;

    if (tid < NS) s_v[tid] = vw[tid];

    // loop t = 0..T: iteration t begins with hybrid barrier A (block 0 does
    // epilogue of step t-1, or priming at t=0, before arriving).
    for (int t = 0; t <= T; t++) {
        if (bid == 0) {
            // wait for all other 127 blocks (their gate writes are fenced pre-arrival)
            if (tid == 0) {
                while (!(ldv(&g_grpCnt[0]) == GS - 1 && ldv(&g_rootCnt) == NGRP - 1)) { }
            }
            __syncthreads();
            if (t == 0) {
                // ---- priming: x0 = [zeros(200), emb[eos]], h=c=0 ----
                if (tid == 0) s_loss = 0.f;
                if (tid < G4) {
                    const float4* wr = (const float4*)(Wih + tid * XD + S2);
                    const float4* ev = (const float4*)(emb + eos * NS);
                    float acc = __ldg(&bih[tid]) + __ldg(&bhh[tid]);
                    #pragma unroll
                    for (int i = 0; i < 25; i++) {
                        float4 wv = __ldg(wr + i), xv = __ldg(ev + i);
                        acc += wv.x * xv.x + wv.y * xv.y + wv.z * xv.z + wv.w * xv.w;
                    }
                    s_g[tid] = acc;
                }
                __syncthreads();
                if (tid < NS) {
                    float gi = s_g[tid], gg = s_g[2 * NS + tid], go = s_g[3 * NS + tid];
                    float cn = sigf(gi) * tanhf(gg);
                    s_c[tid] = cn;
                    float hh = sigf(go) * tanhf(cn);
                    s_h[tid] = hh;
                    g_h[tid] = hh;
                }
                __syncthreads();
            } else {
                // ---- epilogue of step t-1 ----
                float rz = 1.f / (*((volatile float*)&g_Z));
                if (tid < NS) {
                    float gi = __ldcg(&g_gateA[tid])          * rz + __ldcg(&g_gateB[tid]);
                    float gf = __ldcg(&g_gateA[NS + tid])     * rz + __ldcg(&g_gateB[NS + tid]);
                    float gg = __ldcg(&g_gateA[2 * NS + tid]) * rz + __ldcg(&g_gateB[2 * NS + tid]);
                    float go = __ldcg(&g_gateA[3 * NS + tid]) * rz + __ldcg(&g_gateB[3 * NS + tid]);
                    float cn = sigf(gf) * s_c[tid] + sigf(gi) * tanhf(gg);
                    s_c[tid] = cn;
                    float hh = sigf(go) * tanhf(cn);
                    s_h[tid] = hh;
                    g_h[tid] = hh;
                }
                __syncthreads();
                if (tid < NV) {
                    const float4* lr = (const float4*)(linw + tid * NS);
                    const float4* hv = (const float4*)s_h;
                    float acc = __ldg(&linb[tid]);
                    #pragma unroll
                    for (int i = 0; i < 25; i++) {
                        float4 wv = __ldg(lr + i), xv = hv[i];
                        acc += wv.x * xv.x + wv.y * xv.y + wv.z * xv.z + wv.w * xv.w;
                    }
                    s_lg[tid] = acc;
                }
                __syncthreads();
                if (wid == 0) {
                    int ch = __ldg(&ids[t - 1]);
                    float m = fmaxf(fmaxf(s_lg[lane], s_lg[lane + 32]),
                                    fmaxf(s_lg[lane + 64], s_lg[lane + 96]));
                    m = fmaxf(m, __shfl_xor_sync(0xffffffffu, m, 16));
                    m = fmaxf(m, __shfl_xor_sync(0xffffffffu, m, 8));
                    m = fmaxf(m, __shfl_xor_sync(0xffffffffu, m, 4));
                    m = fmaxf(m, __shfl_xor_sync(0xffffffffu, m, 2));
                    m = fmaxf(m, __shfl_xor_sync(0xffffffffu, m, 1));
                    float se = expf(s_lg[lane] - m) + expf(s_lg[lane + 32] - m)
                             + expf(s_lg[lane + 64] - m) + expf(s_lg[lane + 96] - m);
                    se = warp_bfly(se);
                    if (lane == 0) s_loss += logf(se) + m - s_lg[ch];
                }
                __syncthreads();
            }
            // publish w2dt for step t (only if more steps remain)
            if (t < T) {
                if (tid >= 128 && tid < 228) {
                    int a = tid - 128;
                    const float4* wrow = (const float4*)(w2 + a * S2);
                    const float4* hv = (const float4*)s_h;
                    const float4* cv = (const float4*)s_c;
                    float acc = 0.f;
                    #pragma unroll
                    for (int i = 0; i < 25; i++) {
                        float4 wv = __ldg(wrow + i), xv = hv[i];
                        acc += wv.x * xv.x + wv.y * xv.y + wv.z * xv.z + wv.w * xv.w;
                    }
                    #pragma unroll
                    for (int i = 0; i < 25; i++) {
                        float4 wv = __ldg(wrow + 25 + i), xv = cv[i];
                        acc += wv.x * xv.x + wv.y * xv.y + wv.z * xv.z + wv.w * xv.w;
                    }
                    g_w2dt[a] = acc;
                }
            } else {
                if (tid == 0) out[0] = s_loss;
            }
            __syncthreads();
        }
        tbar(bid);                // BAR_A: release == w2dt/h ready (or final)
        if (t == T) break;

        // refresh warp-uniform w2dt into smem
        if (tid < NS) s_w2dt[tid] = __ldcg(&g_w2dt[tid]);
        __syncthreads();

        // ======= attention: per-thread l, shuffle-free =======
        const __half2* wp = g_w1t + (size_t)tile * 1600 + lane;
        float sc = 0.f;
        #pragma unroll 10
        for (int a2 = 0; a2 < 50; a2++) {
            float2 wv = __half22float2(__ldg(wp + a2 * 32));
            float2 vv = *(const float2*)&s_v[2 * a2];
            float2 wd = *(const float2*)&s_w2dt[2 * a2];
            sc += vv.x * tanhapx(wv.x + wd.x) + vv.y * tanhapx(wv.y + wd.y);
        }
        float e = ex2fast((sc + vb0 - Moff) * LOG2E);   // exponent <= 0 by construction
        s_e[wid * 33 + lane] = e;
        __syncwarp();

        float acc[8];
        #pragma unroll
        for (int i = 0; i < 8; i++) acc[i] = 0.f;
        if (lane < 25) {
            const float4* ib = (const float4*)(g_imc + (size_t)tile * 32 * 100);
            const float* ep = s_e + wid * 33;
            #pragma unroll 4
            for (int li = 0; li < 32; li++) {
                float4 r = __ldg(ib + li * 25 + lane);
                float el = ep[li];
                const __half2* hp = (const __half2*)&r;
                float2 f0 = __half22float2(hp[0]);
                float2 f1 = __half22float2(hp[1]);
                float2 f2 = __half22float2(hp[2]);
                float2 f3 = __half22float2(hp[3]);
                acc[0] += el * f0.x; acc[1] += el * f0.y;
                acc[2] += el * f1.x; acc[3] += el * f1.y;
                acc[4] += el * f2.x; acc[5] += el * f2.y;
                acc[6] += el * f3.x; acc[7] += el * f3.y;
            }
            float4* wr = (float4*)(s_w + wid * 208 + 8 * lane);
            wr[0] = make_float4(acc[0], acc[1], acc[2], acc[3]);
            wr[1] = make_float4(acc[4], acc[5], acc[6], acc[7]);
        }
        float z = warp_bfly(e);
        if (lane == 0) s_wz[wid] = z;
        __syncthreads();
        if (tid < S2) {
            float s = 0.f;
            #pragma unroll
            for (int w = 0; w < 16; w++) s += s_w[w * 208 + tid];
            g_partCtxT[tid * NB + bid] = s;
        }
        if (tid == 256) {
            float s = 0.f;
            #pragma unroll
            for (int w = 0; w < 16; w++) s += s_wz[w];
            g_partZ[bid] = s;
        }

        tbar(bid);                // BAR_B: partials visible

        // ======= ctx reduce (distributed) + Z =======
        if (wid == 0) {
            int j = bid;
            float s = 0.f;
            #pragma unroll
            for (int i = 0; i < 4; i++) s += __ldcg(&g_partCtxT[j * NB + lane + 32 * i]);
            s = warp_bfly(s);
            if (lane == 0) g_ctx[j] = s;
        } else if (wid == 1) {
            int j = bid + NB;
            if (j < S2) {
                float s = 0.f;
                #pragma unroll
                for (int i = 0; i < 4; i++) s += __ldcg(&g_partCtxT[j * NB + lane + 32 * i]);
                s = warp_bfly(s);
                if (lane == 0) g_ctx[j] = s;
            }
        } else if (wid == 2 && bid == 0) {
            float s = 0.f;
            #pragma unroll
            for (int i = 0; i < 4; i++) s += __ldcg(&g_partZ[lane + 32 * i]);
            s = warp_bfly(s);
            if (lane == 0) g_Z = s;
        }

        tbar(bid);                // WAVE_C: ctx + Z visible

        // ======= gates (distributed, warp-per-output) =======
        {
            int prev = (t == 0) ? eos : __ldg(&ids[t - 1]);
            if (wid < 4) {
                int k = wid * NB + bid;
                if (k < G4) {
                    const float* wr = Wih + k * XD;
                    float dc = 0.f, d0 = 0.f;
                    #pragma unroll
                    for (int i = 0; i < 7; i++) {
                        int j = lane + 32 * i;
                        if (j < S2) dc += __ldg(wr + j) * __ldcg(&g_ctx[j]);
                    }
                    const float* ep = emb + prev * NS;
                    #pragma unroll
                    for (int i = 0; i < 4; i++) {
                        int j = lane + 32 * i;
                        if (j < NS) d0 += __ldg(wr + S2 + j) * __ldg(ep + j);
                    }
                    const float* hr = Whh + k * NS;
                    #pragma unroll
                    for (int i = 0; i < 4; i++) {
                        int j = lane + 32 * i;
                        if (j < NS) d0 += __ldg(hr + j) * __ldcg(&g_h[j]);
                    }
                    dc = warp_bfly(dc);
                    d0 = warp_bfly(d0);
                    if (lane == 0) {
                        g_gateA[k] = dc;
                        g_gateB[k] = d0 + __ldg(&bih[k]) + __ldg(&bhh[k]);
                    }
                }
            }
        }
        // next iteration's BAR_A doubles as the gate-completion wave
    }
}

// ---------------- launch ----------------
extern "C" void kernel_launch(void* const* d_in, const int* in_sizes, int n_in,
                              void* d_out, int out_size) {
    const float* im   = (const float*)d_in[0];
    const int*   ids  = (const int*)  d_in[1];
    const float* Wih  = (const float*)d_in[2];
    const float* Whh  = (const float*)d_in[3];
    const float* bih  = (const float*)d_in[4];
    const float* bhh  = (const float*)d_in[5];
    const float* w1   = (const float*)d_in[6];
    const float* w2   = (const float*)d_in[7];
    const float* vw   = (const float*)d_in[8];
    const float* vb   = (const float*)d_in[9];
    const float* linw = (const float*)d_in[10];
    const float* linb = (const float*)d_in[11];
    const float* emb  = (const float*)d_in[12];
    const int*   eosp = (n_in > 13) ? (const int*)d_in[13] : nullptr;
    const int T = in_sizes[1];

    k_pre0<<<64, 256>>>(w1, vw, vb);
    k_pre1<<<dim3(LSEQ / 32, 7), dim3(32, 32)>>>(im);
    k_pre2<<<2048, 128>>>();
    k_pre3<<<2048, 256>>>();
    k_main<<<NB, 512>>>(ids, Wih, Whh, bih, bhh, w2, vw, vb, linw, linb, emb,
                        eosp, (float*)d_out, T);
}

// round 5
// speedup vs baseline: 2.1470x; 1.0219x over previous
#include <cuda_runtime.h>
#include <cuda_fp16.h>
#include <math.h>

#define LSEQ 65536
#define NS   100
#define S2   200
#define XD   300
#define G4   400
#define NV   128
#define NB   148
#define NT   2048          // LSEQ/32 tiles
#define NGRP 4
#define GS   37
#define MAXT 14
#define PADB 160
#define LOG2E 1.4426950408889634f

// ---------------- device scratch ----------------
__device__ __align__(128) __half2 g_imc [LSEQ * 100];    // fp16 [l][j2]  13.1 MB
__device__ __align__(128) __half2 g_w1t [NT * 1600];     // fp16 [tile][a2][lane] 13.1 MB
__device__ float g_w1T[S2 * NS];                         // [j][a]
__device__ float g_expC;
__device__ float g_partCtxT[S2 * PADB];                  // [j][b]
__device__ __align__(16) float g_partZ[PADB];
__device__ float g_ctx[S2];
__device__ float g_Z;
__device__ float g_gateA[G4];
__device__ float g_gateB[G4];
__device__ __align__(16) __half2 g_w2dth[50];
__device__ float g_h[NS];
__device__ unsigned g_grpCnt[NGRP * 32];                 // 128B-strided
__device__ unsigned g_rootCnt;
__device__ unsigned g_rootGen;

// ---------------- helpers ----------------
__device__ __forceinline__ float ex2fast(float x) {
    float y; asm("ex2.approx.f32 %0, %1;" : "=f"(y) : "f"(x)); return y;
}
__device__ __forceinline__ __half2 tanh2(__half2 x) {
    unsigned xi = *(unsigned*)&x, yi;
    asm("tanh.approx.f16x2 %0, %1;" : "=r"(yi) : "r"(xi));
    return *(__half2*)&yi;
}
// accurate sigmoid/tanh via ex2+rcp (err ~1e-7)
__device__ __forceinline__ float sigf(float x) {
    float t; asm("ex2.approx.f32 %0, %1;" : "=f"(t) : "f"(-x * LOG2E));
    float r; asm("rcp.approx.f32 %0, %1;" : "=f"(r) : "f"(1.f + t));
    return r;
}
__device__ __forceinline__ float tanh_acc(float x) {
    x = fminf(10.f, fmaxf(-10.f, x));
    float t; asm("ex2.approx.f32 %0, %1;" : "=f"(t) : "f"(x * 2.885390081777927f));
    float r; asm("rcp.approx.f32 %0, %1;" : "=f"(r) : "f"(t + 1.f));
    return (t - 1.f) * r;
}
__device__ __forceinline__ float warp_bfly(float v) {
    v += __shfl_xor_sync(0xffffffffu, v, 16);
    v += __shfl_xor_sync(0xffffffffu, v, 8);
    v += __shfl_xor_sync(0xffffffffu, v, 4);
    v += __shfl_xor_sync(0xffffffffu, v, 2);
    v += __shfl_xor_sync(0xffffffffu, v, 1);
    return v;
}
__device__ __forceinline__ unsigned ldv(unsigned* p) { return *((volatile unsigned*)p); }

// tree barrier: 4 groups of 37 + root
__device__ __forceinline__ void tbar(int bid) {
    __threadfence();
    __syncthreads();
    if (threadIdx.x == 0) {
        int g = bid / GS;
        unsigned gen = ldv(&g_rootGen);
        if (atomicAdd(&g_grpCnt[g * 32], 1u) == GS - 1) {
            atomicExch(&g_grpCnt[g * 32], 0u);
            __threadfence();
            if (atomicAdd(&g_rootCnt, 1u) == NGRP - 1) {
                atomicExch(&g_rootCnt, 0u);
                __threadfence();
                atomicAdd(&g_rootGen, 1u);
            } else {
                while (ldv(&g_rootGen) == gen) { }
            }
        } else {
            while (ldv(&g_rootGen) == gen) { }
        }
    }
    __syncthreads();
}

// ---------------- kA: transpose im -> fp16 imc; w1T; expC ----------------
__global__ void kA(const float* __restrict__ im, const float* __restrict__ w1,
                   const float* __restrict__ vw, const float* __restrict__ vb) {
    __shared__ float tile[32][33];
    int tx = threadIdx.x, ty = threadIdx.y;
    int l0 = blockIdx.x * 32, j0 = blockIdx.y * 32;
    int j = j0 + ty;
    if (j < S2) tile[ty][tx] = im[(size_t)j * LSEQ + l0 + tx];
    __syncthreads();
    int jw = j0 + tx;
    if (jw < S2)
        ((__half*)g_imc)[(size_t)(l0 + ty) * S2 + jw] = __float2half_rn(tile[tx][ty]);

    if (blockIdx.x == 0 && blockIdx.y == 0) {
        int tid = ty * 32 + tx;
        for (int i = tid; i < NS * S2; i += 1024) {
            int a = i / S2, jj = i - a * S2;
            g_w1T[jj * NS + a] = w1[i];
        }
        if (tid == 0) {
            float s = fabsf(vb[0]);
            for (int a = 0; a < NS; a++) s += fabsf(vw[a]);
            g_expC = s;
        }
    }
}

// ---------------- kB: per tile, w1dt = imc @ w1T -> fp16 tiles ----------------
__global__ void kB() {
    __shared__ __align__(16) float rows[32][200];
    __shared__ float souts[32][100];
    int tid = threadIdx.x;
    for (int tile = blockIdx.x; tile < NT; tile += gridDim.x) {
        const __half2* src = g_imc + (size_t)tile * 3200;
        for (int i = tid; i < 3200; i += 256) {
            int l = i / 100, j2 = i - l * 100;
            float2 f = __half22float2(src[i]);
            rows[l][2 * j2] = f.x;
            rows[l][2 * j2 + 1] = f.y;
        }
        __syncthreads();
        if (tid < NS) {
            #pragma unroll
            for (int p = 0; p < 4; p++) {
                float acc[8];
                #pragma unroll
                for (int li = 0; li < 8; li++) acc[li] = 0.f;
                for (int j = 0; j < 200; j += 4) {
                    float w0 = g_w1T[(j + 0) * NS + tid];
                    float w1v = g_w1T[(j + 1) * NS + tid];
                    float w2v = g_w1T[(j + 2) * NS + tid];
                    float w3v = g_w1T[(j + 3) * NS + tid];
                    #pragma unroll
                    for (int li = 0; li < 8; li++) {
                        float4 r = *(const float4*)&rows[p * 8 + li][j];
                        acc[li] += r.x * w0 + r.y * w1v + r.z * w2v + r.w * w3v;
                    }
                }
                #pragma unroll
                for (int li = 0; li < 8; li++) souts[p * 8 + li][tid] = acc[li];
            }
        }
        __syncthreads();
        for (int i = tid; i < 1600; i += 256) {
            int a2 = i >> 5, lane = i & 31;
            g_w1t[(size_t)tile * 1600 + i] =
                __floats2half2_rn(souts[lane][2 * a2], souts[lane][2 * a2 + 1]);
        }
        __syncthreads();
    }
}

// ---------------- persistent main kernel ----------------
__global__ void __launch_bounds__(512, 1) k_main(
    const int*   __restrict__ ids,
    const float* __restrict__ Wih,  const float* __restrict__ Whh,
    const float* __restrict__ bih,  const float* __restrict__ bhh,
    const float* __restrict__ w2,
    const float* __restrict__ vw,   const float* __restrict__ vb,
    const float* __restrict__ linw, const float* __restrict__ linb,
    const float* __restrict__ emb,  const int* __restrict__ eosp,
    float* __restrict__ out, int T)
{
    const int tid  = threadIdx.x, lane = tid & 31, wid = tid >> 5;
    const int bid  = blockIdx.x;
    const int start = (bid * NT) / NB;
    const int cnt   = ((bid + 1) * NT) / NB - start;

    extern __shared__ __align__(16) char dynsm[];
    __half2* s_w1 = (__half2*)dynsm;                 // [MAXT][1600]
    float*   s_w  = (float*)(dynsm + MAXT * 6400);   // [16][208]

    __shared__ float s_e[16 * 33];
    __shared__ float s_wz[16];
    __shared__ __align__(16) float s_vv[NS];
    __shared__ __align__(16) __half2 s_wdh[52];
    __shared__ __align__(16) float s_h[NS];
    __shared__ __align__(16) float s_c[NS];
    __shared__ __align__(16) float s_g[G4];
    __shared__ __align__(16) float s_hb[NS];
    __shared__ float s_loss;

    const float vb0  = vb[0];
    const float Moff = g_expC;
    const int   eos  = eosp ? *eosp : 0;

    // ---- one-time init ----
    {
        const float4* src = (const float4*)(g_w1t + (size_t)start * 1600);
        for (int i = tid; i < cnt * 400; i += 512) ((float4*)s_w1)[i] = src[i];
        for (int i = tid; i < 16 * 208; i += 512) s_w[i] = 0.f;
        if (tid < NS) s_vv[tid] = vw[tid];
        if (tid < 16) s_wz[tid] = 0.f;
        if (bid == 1 && tid == 0) s_loss = 0.f;
    }
    __syncthreads();

    for (int t = 0; t <= T; t++) {
        // ================= BAR_A (hybrid): block 0 epilogue inside =================
        if (bid == 0) {
            if (tid == 0) {
                while (!(ldv(&g_grpCnt[0]) == GS - 1 && ldv(&g_rootCnt) == NGRP - 1)) { }
            }
            __syncthreads();
            if (t == 0) {
                // priming: x0 = [zeros(200), emb[eos]], h=c=0
                if (tid < G4) {
                    const float4* wr = (const float4*)(Wih + tid * XD + S2);
                    const float4* ev = (const float4*)(emb + eos * NS);
                    float acc = __ldg(&bih[tid]) + __ldg(&bhh[tid]);
                    #pragma unroll
                    for (int i = 0; i < 25; i++) {
                        float4 wv = __ldg(wr + i), xv = __ldg(ev + i);
                        acc += wv.x * xv.x + wv.y * xv.y + wv.z * xv.z + wv.w * xv.w;
                    }
                    s_g[tid] = acc;
                }
                __syncthreads();
                if (tid < NS) {
                    float gi = s_g[tid], gg = s_g[2 * NS + tid], go = s_g[3 * NS + tid];
                    float cn = sigf(gi) * tanh_acc(gg);
                    s_c[tid] = cn;
                    float hh = sigf(go) * tanh_acc(cn);
                    s_h[tid] = hh;
                    g_h[tid] = hh;
                }
                __syncthreads();
            } else {
                float rz = 1.f / (*((volatile float*)&g_Z));
                if (tid < NS) {
                    float gi = __ldcg(&g_gateA[tid])          * rz + __ldcg(&g_gateB[tid]);
                    float gf = __ldcg(&g_gateA[NS + tid])     * rz + __ldcg(&g_gateB[NS + tid]);
                    float gg = __ldcg(&g_gateA[2 * NS + tid]) * rz + __ldcg(&g_gateB[2 * NS + tid]);
                    float go = __ldcg(&g_gateA[3 * NS + tid]) * rz + __ldcg(&g_gateB[3 * NS + tid]);
                    float cn = sigf(gf) * s_c[tid] + sigf(gi) * tanh_acc(gg);
                    s_c[tid] = cn;
                    float hh = sigf(go) * tanh_acc(cn);
                    s_h[tid] = hh;
                    g_h[tid] = hh;
                }
                __syncthreads();
            }
            if (t < T) {
                // w2dt = w2 @ [h;c]  (100 threads, L1-resident float4 rows)
                if (tid < NS) {
                    const float4* wrow = (const float4*)(w2 + tid * S2);
                    const float4* hv = (const float4*)s_h;
                    const float4* cv = (const float4*)s_c;
                    float acc = 0.f;
                    #pragma unroll
                    for (int i = 0; i < 25; i++) {
                        float4 wv = __ldg(wrow + i), xv = hv[i];
                        acc += wv.x * xv.x + wv.y * xv.y + wv.z * xv.z + wv.w * xv.w;
                    }
                    #pragma unroll
                    for (int i = 0; i < 25; i++) {
                        float4 wv = __ldg(wrow + 25 + i), xv = cv[i];
                        acc += wv.x * xv.x + wv.y * xv.y + wv.z * xv.z + wv.w * xv.w;
                    }
                    s_g[tid] = acc;
                }
                __syncthreads();
                if (tid < 50)
                    g_w2dth[tid] = __floats2half2_rn(s_g[2 * tid], s_g[2 * tid + 1]);
            }
        }
        tbar(bid);                 // release == h (+w2dth) for step t visible

        // ---- block 1 warp 15: loss for step t-1 (off critical path) ----
        if (bid == 1 && wid == 15 && t > 0) {
            for (int i = lane; i < NS; i += 32) s_hb[i] = __ldcg(&g_h[i]);
            __syncwarp();
            int ch = __ldg(&ids[t - 1]);
            float lg[4];
            #pragma unroll
            for (int k = 0; k < 4; k++) {
                int row = lane + 32 * k;
                const float4* lr = (const float4*)(linw + row * NS);
                const float4* hv = (const float4*)s_hb;
                float acc = __ldg(&linb[row]);
                #pragma unroll
                for (int i = 0; i < 25; i++) {
                    float4 wv = __ldg(lr + i), xv = hv[i];
                    acc += wv.x * xv.x + wv.y * xv.y + wv.z * xv.z + wv.w * xv.w;
                }
                lg[k] = acc;
            }
            float m = fmaxf(fmaxf(lg[0], lg[1]), fmaxf(lg[2], lg[3]));
            m = fmaxf(m, __shfl_xor_sync(0xffffffffu, m, 16));
            m = fmaxf(m, __shfl_xor_sync(0xffffffffu, m, 8));
            m = fmaxf(m, __shfl_xor_sync(0xffffffffu, m, 4));
            m = fmaxf(m, __shfl_xor_sync(0xffffffffu, m, 2));
            m = fmaxf(m, __shfl_xor_sync(0xffffffffu, m, 1));
            float se = expf(lg[0] - m) + expf(lg[1] - m) + expf(lg[2] - m) + expf(lg[3] - m);
            se = warp_bfly(se);
            float tg = 0.f;
            #pragma unroll
            for (int k = 0; k < 4; k++) if (lane + 32 * k == ch) tg = lg[k];
            tg = warp_bfly(tg);
            if (lane == 0) s_loss += logf(se) + m - tg;
            if (t == T && lane == 0) out[0] = s_loss;
        }
        if (t == T) break;

        if (tid < 50) s_wdh[tid] = g_w2dth[tid];     // L2 read (fresh via release)
        __syncthreads();

        // ================= attention =================
        if (wid < cnt) {
            const int lt = wid;
            const __half2* wt = s_w1 + lt * 1600 + lane;
            float sc = 0.f;
            #pragma unroll
            for (int a2 = 0; a2 < 50; a2++) {
                __half2 arg = __hadd2(wt[a2 * 32], s_wdh[a2]);
                float2 tf = __half22float2(tanh2(arg));
                float2 vv = *(const float2*)&s_vv[2 * a2];
                sc += vv.x * tf.x + vv.y * tf.y;
            }
            float e = ex2fast((sc + vb0 - Moff) * LOG2E);
            s_e[wid * 33 + lane] = e;
            __syncwarp();

            if (lane < 25) {
                float acc[8];
                #pragma unroll
                for (int i = 0; i < 8; i++) acc[i] = 0.f;
                const float4* ib = (const float4*)(g_imc + (size_t)(start + lt) * 3200);
                const float* ep = s_e + wid * 33;
                #pragma unroll 4
                for (int li = 0; li < 32; li++) {
                    float4 r = __ldg(ib + li * 25 + lane);
                    float el = ep[li];
                    const __half2* hp = (const __half2*)&r;
                    float2 f0 = __half22float2(hp[0]);
                    float2 f1 = __half22float2(hp[1]);
                    float2 f2 = __half22float2(hp[2]);
                    float2 f3 = __half22float2(hp[3]);
                    acc[0] += el * f0.x; acc[1] += el * f0.y;
                    acc[2] += el * f1.x; acc[3] += el * f1.y;
                    acc[4] += el * f2.x; acc[5] += el * f2.y;
                    acc[6] += el * f3.x; acc[7] += el * f3.y;
                }
                float4* wr = (float4*)(s_w + wid * 208 + 8 * lane);
                wr[0] = make_float4(acc[0], acc[1], acc[2], acc[3]);
                wr[1] = make_float4(acc[4], acc[5], acc[6], acc[7]);
            }
            float z = warp_bfly(e);
            if (lane == 0) s_wz[wid] = z;
        }
        __syncthreads();
        if (tid < S2) {
            float s = 0.f;
            #pragma unroll
            for (int w = 0; w < 16; w++) s += s_w[w * 208 + tid];
            g_partCtxT[tid * PADB + bid] = s;
        }
        if (tid == 256) {
            float s = 0.f;
            #pragma unroll
            for (int w = 0; w < 16; w++) s += s_wz[w];
            g_partZ[bid] = s;
        }

        tbar(bid);                 // BAR_B: partials visible

        // ================= ctx reduce + Z =================
        if (wid == 0) {
            int j = bid;
            float s = 0.f;
            #pragma unroll
            for (int i = 0; i < 5; i++) {
                int b = lane + 32 * i;
                if (b < NB) s += __ldcg(&g_partCtxT[j * PADB + b]);
            }
            s = warp_bfly(s);
            if (lane == 0) g_ctx[j] = s;
        } else if (wid == 1) {
            int j = bid + NB;
            if (j < S2) {
                float s = 0.f;
                #pragma unroll
                for (int i = 0; i < 5; i++) {
                    int b = lane + 32 * i;
                    if (b < NB) s += __ldcg(&g_partCtxT[j * PADB + b]);
                }
                s = warp_bfly(s);
                if (lane == 0) g_ctx[j] = s;
            }
        } else if (wid == 2 && bid == 0) {
            float s = 0.f;
            #pragma unroll
            for (int i = 0; i < 5; i++) {
                int b = lane + 32 * i;
                if (b < NB) s += __ldcg(&g_partZ[b]);
            }
            s = warp_bfly(s);
            if (lane == 0) g_Z = s;
        }

        tbar(bid);                 // BAR_C: ctx + Z visible

        // ================= gates (warp-per-output) =================
        {
            int prev = (t == 0) ? eos : __ldg(&ids[t - 1]);
            if (wid < 3) {
                int k = wid * NB + bid;
                if (k < G4) {
                    const float* wr = Wih + k * XD;
                    float dc = 0.f, d0 = 0.f;
                    #pragma unroll
                    for (int i = 0; i < 7; i++) {
                        int j = lane + 32 * i;
                        if (j < S2) dc += __ldg(wr + j) * __ldcg(&g_ctx[j]);
                    }
                    const float* ep = emb + prev * NS;
                    #pragma unroll
                    for (int i = 0; i < 4; i++) {
                        int j = lane + 32 * i;
                        if (j < NS) d0 += __ldg(wr + S2 + j) * __ldg(ep + j);
                    }
                    const float* hr = Whh + k * NS;
                    #pragma unroll
                    for (int i = 0; i < 4; i++) {
                        int j = lane + 32 * i;
                        if (j < NS) d0 += __ldg(hr + j) * __ldcg(&g_h[j]);
                    }
                    dc = warp_bfly(dc);
                    d0 = warp_bfly(d0);
                    if (lane == 0) {
                        g_gateA[k] = dc;
                        g_gateB[k] = d0 + __ldg(&bih[k]) + __ldg(&bhh[k]);
                    }
                }
            }
        }
        // next BAR_A doubles as gate-completion wave
    }
}

// ---------------- launch ----------------
extern "C" void kernel_launch(void* const* d_in, const int* in_sizes, int n_in,
                              void* d_out, int out_size) {
    const float* im   = (const float*)d_in[0];
    const int*   ids  = (const int*)  d_in[1];
    const float* Wih  = (const float*)d_in[2];
    const float* Whh  = (const float*)d_in[3];
    const float* bih  = (const float*)d_in[4];
    const float* bhh  = (const float*)d_in[5];
    const float* w1   = (const float*)d_in[6];
    const float* w2   = (const float*)d_in[7];
    const float* vw   = (const float*)d_in[8];
    const float* vb   = (const float*)d_in[9];
    const float* linw = (const float*)d_in[10];
    const float* linb = (const float*)d_in[11];
    const float* emb  = (const float*)d_in[12];
    const int*   eosp = (n_in > 13) ? (const int*)d_in[13] : nullptr;
    const int T = in_sizes[1];

    static int smem_set = 0;
    const int dyn = MAXT * 6400 + 16 * 208 * 4;   // 102912 B
    if (!smem_set) {
        cudaFuncSetAttribute(k_main, cudaFuncAttributeMaxDynamicSharedMemorySize, dyn);
        smem_set = 1;
    }

    kA<<<dim3(LSEQ / 32, 7), dim3(32, 32)>>>(im, w1, vw, vb);
    kB<<<512, 256>>>();
    k_main<<<NB, 512, dyn>>>(ids, Wih, Whh, bih, bhh, w2, vw, vb, linw, linb,
                             emb, eosp, (float*)d_out, T);
}